// round 15
// baseline (speedup 1.0000x reference)
#include <cuda_runtime.h>
#include <stdint.h>

// PHM embedding: out[tok, q*256 + j] = sum_k a[k,p,q] * s[k,i,j]
//   t = input[tok]; p = t / 12565; i = t % 12565
//   a: [4,4,4] (k,p,q) f32 ; s: [4,12565,256] f32 ; out: [16384,1024] f32
//
// Locked best config (R13): MLP-8 (8 tok x 32 lanes), __launch_bounds__(256,5),
// cache_hint evict_first stores. Micro-tuned: no bounds check (n_tok % 8 == 0),
// token load hoisted to the very top, unsigned strength-reduced indexing to
// shorten the inp-load -> divide -> address -> LDG critical head.

static constexpr unsigned N_ROWS = 12565u;  // VOCAB_PAD / 4
static constexpr unsigned EV4    = 64u;     // 256 f32 cols / 4 per float4
static constexpr unsigned TOK_PER_BLK = 8u;
static constexpr unsigned PLANE4 = N_ROWS * EV4;  // k-plane stride in float4

__device__ __forceinline__ void stg_stream(float4* p, float4 v, uint64_t pol) {
    asm volatile("st.global.L2::cache_hint.v4.f32 [%0], {%1,%2,%3,%4}, %5;"
                 :: "l"(p), "f"(v.x), "f"(v.y), "f"(v.z), "f"(v.w), "l"(pol)
                 : "memory");
}

__global__ void __launch_bounds__(256, 5)
phm_embed_kernel(const int* __restrict__ inp,
                 const float* __restrict__ a,
                 const float4* __restrict__ s,
                 float4* __restrict__ out)
{
    const unsigned lane = threadIdx.x & 31u;   // first float4 column
    const unsigned tsub = threadIdx.x >> 5;    // token within block (0..7)
    const unsigned tok  = blockIdx.x * TOK_PER_BLK + tsub;

    // Critical head: get the token in flight immediately.
    const unsigned t = (unsigned)inp[tok];
    const unsigned p = t / N_ROWS;             // magic-number divide
    const unsigned i = t - p * N_ROWS;

    const float4* srow = s + (size_t)i * EV4 + lane;

    // 8 independent loads front-batched: 4 k-rows x 2 column vectors.
    float4 svA0 = __ldg(srow);
    float4 svB0 = __ldg(srow + 32);
    float4 svA1 = __ldg(srow + PLANE4);
    float4 svB1 = __ldg(srow + PLANE4 + 32);
    float4 svA2 = __ldg(srow + 2 * PLANE4);
    float4 svB2 = __ldg(srow + 2 * PLANE4 + 32);
    float4 svA3 = __ldg(srow + 3 * PLANE4);
    float4 svB3 = __ldg(srow + 3 * PLANE4 + 32);

    uint64_t pol_stream;
    asm volatile("createpolicy.fractional.L2::evict_first.b64 %0, 1.0;"
                 : "=l"(pol_stream));

    // a[k,p,q] = a[k*16 + p*4 + q]; broadcast loads, L1-resident.
    const float* ap = a + p * 4u;

    float4* outp = out + (size_t)tok * 256u + lane;   // 256 float4 per token

#pragma unroll
    for (unsigned q = 0; q < 4; q++) {
        const float c0 = __ldg(&ap[ 0 + q]);
        const float c1 = __ldg(&ap[16 + q]);
        const float c2 = __ldg(&ap[32 + q]);
        const float c3 = __ldg(&ap[48 + q]);

        float4 oA, oB;
        oA.x = c0 * svA0.x + c1 * svA1.x + c2 * svA2.x + c3 * svA3.x;
        oA.y = c0 * svA0.y + c1 * svA1.y + c2 * svA2.y + c3 * svA3.y;
        oA.z = c0 * svA0.z + c1 * svA1.z + c2 * svA2.z + c3 * svA3.z;
        oA.w = c0 * svA0.w + c1 * svA1.w + c2 * svA2.w + c3 * svA3.w;

        oB.x = c0 * svB0.x + c1 * svB1.x + c2 * svB2.x + c3 * svB3.x;
        oB.y = c0 * svB0.y + c1 * svB1.y + c2 * svB2.y + c3 * svB3.y;
        oB.z = c0 * svB0.z + c1 * svB1.z + c2 * svB2.z + c3 * svB3.z;
        oB.w = c0 * svB0.w + c1 * svB1.w + c2 * svB2.w + c3 * svB3.w;

        stg_stream(outp + q * EV4,       oA, pol_stream);
        stg_stream(outp + q * EV4 + 32u, oB, pol_stream);
    }
}

extern "C" void kernel_launch(void* const* d_in, const int* in_sizes, int n_in,
                              void* d_out, int out_size)
{
    const int*    inp = (const int*)d_in[0];    // [8,2048] int32
    const float*  a   = (const float*)d_in[1];  // [4,4,4]
    const float4* s   = (const float4*)d_in[2]; // [4,12565,256] f32 as float4
    float4*       out = (float4*)d_out;

    const int n_tok = in_sizes[0];              // 16384 (multiple of 8)
    const int grid  = n_tok / (int)TOK_PER_BLK; // 2048, exact
    phm_embed_kernel<<<grid, 256>>>(inp, a, s, out);
}

// round 16
// speedup vs baseline: 1.0171x; 1.0171x over previous
#include <cuda_runtime.h>
#include <stdint.h>

// PHM embedding: out[tok, q*256 + j] = sum_k a[k,p,q] * s[k,i,j]
//   t = input[tok]; p = t / 12565; i = t % 12565
//   a: [4,4,4] (k,p,q) f32 ; s: [4,12565,256] f32 ; out: [16384,1024] f32
//
// FINAL (measured optimum, R13 config): MLP-8 layout (8 tokens x 32 lanes,
// 8 front-batched LDG.128 per thread), __launch_bounds__(256,5) to hold
// ~48 regs / 40 warps/SM, and L2::cache_hint evict_first output stores
// (the only store mode that also removes inter-replay writeback drain).
// Kernel is DRAM-throughput bound (~115MB/replay @ ~85% of spec BW);
// all residency/structural levers were probed and are inert on this part.

static constexpr int N_ROWS = 12565;   // VOCAB_PAD / 4
static constexpr int EV4    = 64;      // 256 f32 cols / 4 per float4
static constexpr int TOK_PER_BLK = 8;

__device__ __forceinline__ void stg_stream(float4* p, float4 v, uint64_t pol) {
    asm volatile("st.global.L2::cache_hint.v4.f32 [%0], {%1,%2,%3,%4}, %5;"
                 :: "l"(p), "f"(v.x), "f"(v.y), "f"(v.z), "f"(v.w), "l"(pol)
                 : "memory");
}

__global__ void __launch_bounds__(256, 5)
phm_embed_kernel(const int* __restrict__ inp,
                 const float* __restrict__ a,
                 const float4* __restrict__ s,
                 float4* __restrict__ out,
                 int n_tok)
{
    const int lane = threadIdx.x & 31;        // first float4 column
    const int tsub = threadIdx.x >> 5;        // token within block (0..7)
    const int tok  = blockIdx.x * TOK_PER_BLK + tsub;
    if (tok >= n_tok) return;

    const int t = inp[tok];
    const int p = t / N_ROWS;                 // compile-time magic divide
    const int i = t - p * N_ROWS;

    const float4* srow = s + (size_t)i * EV4 + lane;

    // 8 independent loads front-batched: 4 k-rows x 2 column vectors.
    float4 svA0 = __ldg(srow + 0 * N_ROWS * EV4);
    float4 svB0 = __ldg(srow + 0 * N_ROWS * EV4 + 32);
    float4 svA1 = __ldg(srow + 1 * N_ROWS * EV4);
    float4 svB1 = __ldg(srow + 1 * N_ROWS * EV4 + 32);
    float4 svA2 = __ldg(srow + 2 * N_ROWS * EV4);
    float4 svB2 = __ldg(srow + 2 * N_ROWS * EV4 + 32);
    float4 svA3 = __ldg(srow + 3 * N_ROWS * EV4);
    float4 svB3 = __ldg(srow + 3 * N_ROWS * EV4 + 32);

    uint64_t pol_stream;
    asm volatile("createpolicy.fractional.L2::evict_first.b64 %0, 1.0;"
                 : "=l"(pol_stream));

    // a[k,p,q] = a[k*16 + p*4 + q]; broadcast loads, L1-resident.
    const float* ap = a + p * 4;

    float4* outp = out + (size_t)tok * 256 + lane;   // 256 float4 per token

#pragma unroll
    for (int q = 0; q < 4; q++) {
        const float c0 = __ldg(&ap[ 0 + q]);
        const float c1 = __ldg(&ap[16 + q]);
        const float c2 = __ldg(&ap[32 + q]);
        const float c3 = __ldg(&ap[48 + q]);

        float4 oA, oB;
        oA.x = c0 * svA0.x + c1 * svA1.x + c2 * svA2.x + c3 * svA3.x;
        oA.y = c0 * svA0.y + c1 * svA1.y + c2 * svA2.y + c3 * svA3.y;
        oA.z = c0 * svA0.z + c1 * svA1.z + c2 * svA2.z + c3 * svA3.z;
        oA.w = c0 * svA0.w + c1 * svA1.w + c2 * svA2.w + c3 * svA3.w;

        oB.x = c0 * svB0.x + c1 * svB1.x + c2 * svB2.x + c3 * svB3.x;
        oB.y = c0 * svB0.y + c1 * svB1.y + c2 * svB2.y + c3 * svB3.y;
        oB.z = c0 * svB0.z + c1 * svB1.z + c2 * svB2.z + c3 * svB3.z;
        oB.w = c0 * svB0.w + c1 * svB1.w + c2 * svB2.w + c3 * svB3.w;

        stg_stream(outp + q * EV4,      oA, pol_stream);
        stg_stream(outp + q * EV4 + 32, oB, pol_stream);
    }
}

extern "C" void kernel_launch(void* const* d_in, const int* in_sizes, int n_in,
                              void* d_out, int out_size)
{
    const int*    inp = (const int*)d_in[0];    // [8,2048] int32
    const float*  a   = (const float*)d_in[1];  // [4,4,4]
    const float4* s   = (const float4*)d_in[2]; // [4,12565,256] f32 as float4
    float4*       out = (float4*)d_out;

    const int n_tok = in_sizes[0];              // 16384
    const int grid  = (n_tok + TOK_PER_BLK - 1) / TOK_PER_BLK;
    phm_embed_kernel<<<grid, 256>>>(inp, a, s, out, n_tok);
}